// round 9
// baseline (speedup 1.0000x reference)
#include <cuda_runtime.h>
#include <cuda_bf16.h>

// Causal depthwise conv1d (K=4) + SiLU over x:(B,S,D) fp32, channel-innermost.
// y[b,s,d] = silu( sum_{k=0..3} w[d,0,k] * x[b, s-3+k, d] )  (zero left-pad)
//
// R8: forced-occupancy experiment. R3/R4/R5/R6 all converge to ~80.5us ncu,
// DRAM ~78%, 6.2TB/s, regs=48 regardless of tiling -> ptxas won't shrink regs
// voluntarily. Force it:
//  - __launch_bounds__(128, 12): cap 42 regs -> 12 blocks/SM -> 48 warps.
//  - single running pointer + constant x->y byte delta (saves a pointer pair
//    and an increment) to help the body fit 42 regs without spills.
//  - CHUNK=16, GROUP=4 batched LDG.128, __fdividef SiLU, __stcs stores.

#define TPB   128
#define CHUNK 16
#define GROUP 4

__device__ __forceinline__ float silu_fast(float v) {
    return __fdividef(v, 1.0f + __expf(-v));
}

__global__ __launch_bounds__(TPB, 12)
void causal_conv1d_silu_kernel(const float4* __restrict__ x,
                               const float4* __restrict__ w,   // (D,1,K) -> per-channel float4 taps
                               float4* __restrict__ y,
                               int S, int D4)
{
    const int d4 = blockIdx.x * TPB + threadIdx.x;   // float4-channel group
    const int s0 = blockIdx.y * CHUNK;
    const int b  = blockIdx.z;

    const float4 w0 = w[4 * d4 + 0];
    const float4 w1 = w[4 * d4 + 1];
    const float4 w2 = w[4 * d4 + 2];
    const float4 w3 = w[4 * d4 + 3];

    // Max element index = 4*8192*512 = 16.7M -> int32 is safe.
    const int idx = (b * S + s0) * D4 + d4;
    const float4* __restrict__ xp = x + idx;
    // One pointer walks x; y addresses derived via constant byte delta.
    const ptrdiff_t ydelta = (const char*)y - (const char*)x;

    // History: p1 = x[s0-1], p2 = x[s0-2], p3 = x[s0-3] (zero before s=0).
    const float4 z = make_float4(0.f, 0.f, 0.f, 0.f);
    float4 p1 = z, p2 = z, p3 = z;
    if (s0 >= 3) {
        p1 = xp[-1 * D4];
        p2 = xp[-2 * D4];
        p3 = xp[-3 * D4];
    }

    #pragma unroll
    for (int g = 0; g < CHUNK; g += GROUP) {
        // Batched loads: GROUP independent LDG.128 in flight before compute.
        float4 c[GROUP];
        #pragma unroll
        for (int j = 0; j < GROUP; ++j)
            c[j] = xp[j * D4];

        #pragma unroll
        for (int j = 0; j < GROUP; ++j) {
            const float4 cur = c[j];
            float4 r;
            // taps: k=0 -> x[s-3] (oldest) ... k=3 -> x[s]
            r.x = w0.x * p3.x + w0.y * p2.x + w0.z * p1.x + w0.w * cur.x;
            r.y = w1.x * p3.y + w1.y * p2.y + w1.z * p1.y + w1.w * cur.y;
            r.z = w2.x * p3.z + w2.y * p2.z + w2.z * p1.z + w2.w * cur.z;
            r.w = w3.x * p3.w + w3.y * p2.w + w3.z * p1.w + w3.w * cur.w;

            r.x = silu_fast(r.x);
            r.y = silu_fast(r.y);
            r.z = silu_fast(r.z);
            r.w = silu_fast(r.w);

            float4* yj = (float4*)((char*)(xp + j * D4) + ydelta);
            __stcs(yj, r);

            p3 = p2; p2 = p1; p1 = cur;
        }

        xp += GROUP * D4;
    }
}

extern "C" void kernel_launch(void* const* d_in, const int* in_sizes, int n_in,
                              void* d_out, int out_size)
{
    const float* x = (const float*)d_in[0];
    const float* w = (const float*)d_in[1];
    float*       y = (float*)d_out;

    const int K = 4;
    const int D = in_sizes[1] / K;          // 2048
    const int S = 8192;
    const int B = in_sizes[0] / (S * D);    // 4

    const int D4 = D / 4;                   // 512

    dim3 block(TPB);
    dim3 grid(D4 / TPB, S / CHUNK, B);      // (4, 512, 4) = 8192 blocks

    causal_conv1d_silu_kernel<<<grid, block>>>(
        (const float4*)x, (const float4*)w, (float4*)y, S, D4);
}

// round 10
// speedup vs baseline: 1.5701x; 1.5701x over previous
#include <cuda_runtime.h>
#include <cuda_bf16.h>

// Causal depthwise conv1d (K=4) + SiLU over x:(B,S,D) fp32, channel-innermost.
// y[b,s,d] = silu( sum_{k=0..3} w[d,0,k] * x[b, s-3+k, d] )  (zero left-pad)
//
// R9: final configuration. Evidence across R3-R8:
//  - traffic is at the 512MB floor; 6.2-6.3 TB/s (~78% of 8TB/s) is the
//    sustained ceiling for this 50/50 R/W stream (tiling/occupancy invariant).
//  - regs=48 is the true live set: capping to 42 (R8) spilled to local and
//    cost +62% runtime. No launch_bounds cap.
//  - best wall config: CHUNK=16, GROUP=8, TPB=128 (R5).
//  - new: __ldcg for x loads — x has zero in-block L1 reuse (halo reuse is
//    cross-block, served by L2); skip L1 allocation on the bulk stream.
//  - __fdividef SiLU (MUFU RCP), __stcs 128-bit streaming stores.

#define TPB   128
#define CHUNK 16
#define GROUP 8

__device__ __forceinline__ float silu_fast(float v) {
    return __fdividef(v, 1.0f + __expf(-v));
}

__global__ __launch_bounds__(TPB)
void causal_conv1d_silu_kernel(const float4* __restrict__ x,
                               const float4* __restrict__ w,   // (D,1,K) -> per-channel float4 taps
                               float4* __restrict__ y,
                               int S, int D4)
{
    const int d4 = blockIdx.x * TPB + threadIdx.x;   // float4-channel group
    const int s0 = blockIdx.y * CHUNK;
    const int b  = blockIdx.z;

    const float4 w0 = w[4 * d4 + 0];
    const float4 w1 = w[4 * d4 + 1];
    const float4 w2 = w[4 * d4 + 2];
    const float4 w3 = w[4 * d4 + 3];

    const size_t st   = (size_t)D4;
    const size_t base = ((size_t)b * S + s0) * st + (size_t)d4;

    // History: p1 = x[s0-1], p2 = x[s0-2], p3 = x[s0-3] (zero before s=0).
    const float4 z = make_float4(0.f, 0.f, 0.f, 0.f);
    float4 p1 = z, p2 = z, p3 = z;
    if (s0 >= 3) {
        p1 = __ldcg(&x[base - 1 * st]);
        p2 = __ldcg(&x[base - 2 * st]);
        p3 = __ldcg(&x[base - 3 * st]);
    }

    #pragma unroll
    for (int g = 0; g < CHUNK; g += GROUP) {
        // Batched loads: GROUP independent LDG.128.CG in flight before compute.
        float4 c[GROUP];
        #pragma unroll
        for (int j = 0; j < GROUP; ++j)
            c[j] = __ldcg(&x[base + (size_t)(g + j) * st]);

        #pragma unroll
        for (int j = 0; j < GROUP; ++j) {
            const float4 cur = c[j];
            float4 r;
            // taps: k=0 -> x[s-3] (oldest) ... k=3 -> x[s]
            r.x = w0.x * p3.x + w0.y * p2.x + w0.z * p1.x + w0.w * cur.x;
            r.y = w1.x * p3.y + w1.y * p2.y + w1.z * p1.y + w1.w * cur.y;
            r.z = w2.x * p3.z + w2.y * p2.z + w2.z * p1.z + w2.w * cur.z;
            r.w = w3.x * p3.w + w3.y * p2.w + w3.z * p1.w + w3.w * cur.w;

            r.x = silu_fast(r.x);
            r.y = silu_fast(r.y);
            r.z = silu_fast(r.z);
            r.w = silu_fast(r.w);

            __stcs(&y[base + (size_t)(g + j) * st], r);

            p3 = p2; p2 = p1; p1 = cur;
        }
    }
}

extern "C" void kernel_launch(void* const* d_in, const int* in_sizes, int n_in,
                              void* d_out, int out_size)
{
    const float* x = (const float*)d_in[0];
    const float* w = (const float*)d_in[1];
    float*       y = (float*)d_out;

    const int K = 4;
    const int D = in_sizes[1] / K;          // 2048
    const int S = 8192;
    const int B = in_sizes[0] / (S * D);    // 4

    const int D4 = D / 4;                   // 512

    dim3 block(TPB);
    dim3 grid(D4 / TPB, S / CHUNK, B);      // (4, 512, 4) = 8192 blocks

    causal_conv1d_silu_kernel<<<grid, block>>>(
        (const float4*)x, (const float4*)w, (float4*)y, S, D4);
}